// round 13
// baseline (speedup 1.0000x reference)
#include <cuda_runtime.h>
#include <cuda_bf16.h>
#include <math_constants.h>

#define NNODES 100000
#define FIN 512
#define F1 16
#define F2P 8      // 7 padded to 8
#define EMAX 3400000

// ---------------- scratch (no allocations allowed) ----------------
__device__ int g_cnt[NNODES];          // in-degree (excl. self-loop)
__device__ int g_rowptr[NNODES + 1];   // CSR row offsets (by target)
__device__ int g_cursor[NNODES];       // fill cursors
__device__ int g_src[EMAX];            // source index per CSR slot
__device__ __align__(16) float g_y1[NNODES * F1];    // dinv[r]*xw1[r]
__device__ __align__(16) float g_acc1[NNODES * F1];  // y1[i] + sum_in y1[r]
__device__ __align__(16) float g_y2[NNODES * F2P];
__device__ __align__(16) float g_acc2[NNODES * F2P];
__device__ int g_is64;   // edge dtype flag (1 = int64, 0 = int32)

// ---------------- helpers ----------------
__device__ __forceinline__ unsigned long long fma2(unsigned long long a,
                                                   unsigned long long b,
                                                   unsigned long long c) {
    unsigned long long d;
    asm("fma.rn.f32x2 %0, %1, %2, %3;" : "=l"(d) : "l"(a), "l"(b), "l"(c));
    return d;
}
__device__ __forceinline__ unsigned long long mul2(unsigned long long a,
                                                   unsigned long long b) {
    unsigned long long d;
    asm("mul.rn.f32x2 %0, %1, %2;" : "=l"(d) : "l"(a), "l"(b));
    return d;
}
__device__ __forceinline__ unsigned long long pack2(float x) {
    unsigned long long d;
    unsigned xi = __float_as_uint(x);
    asm("mov.b64 %0, {%1, %1};" : "=l"(d) : "r"(xi));
    return d;
}

// Layout: planar [all sources | all targets], E entries per block.
__device__ __forceinline__ void load_edge(const void* ei, int E, int e,
                                          int& r, int& c) {
    if (g_is64) {
        const long long* p = (const long long*)ei;
        r = (int)p[e];
        c = (int)p[(size_t)E + e];
    } else {
        const int* p = (const int*)ei;
        r = p[e];
        c = p[(size_t)E + e];
    }
}
__device__ __forceinline__ int load_col(const void* ei, int E, int e) {
    if (g_is64) return (int)((const long long*)ei)[(size_t)E + e];
    return ((const int*)ei)[(size_t)E + e];
}

// ---------------- kernels ----------------

// fused: dtype probe (global thread 0) + zero counts.
__global__ void k_setup(const void* ei, int n) {
    int i = blockIdx.x * blockDim.x + threadIdx.x;
    if (i == 0) {
        const long long* p = (const long long*)ei;
        int ok = 1;
        for (int j = 0; j < 1024; j++) {
            long long v = p[j];
            if (v < 0 || v >= (long long)n) { ok = 0; break; }
        }
        g_is64 = ok;
    }
    if (i < n) g_cnt[i] = 0;
}

// in-degree histogram (int atomics -- cheap)
__global__ void k_count(const void* __restrict__ ei, int E, int n) {
    int e = blockIdx.x * blockDim.x + threadIdx.x;
    if (e >= E) return;
    int c = load_col(ei, E, e);
    if ((unsigned)c >= (unsigned)n) return;
    atomicAdd(&g_cnt[c], 1);
}

// single-block exclusive prefix sum over n counts -> rowptr, cursor
__global__ void __launch_bounds__(1024) k_scan(int n) {
    __shared__ int s[1024];
    int tid = threadIdx.x;
    int per = (n + 1023) / 1024;
    int lo = tid * per;
    int hi = min(n, lo + per);
    int sum = 0;
    for (int i = lo; i < hi; i++) sum += g_cnt[i];
    s[tid] = sum;
    __syncthreads();
    if (tid == 0) {
        int run = 0;
        for (int t = 0; t < 1024; t++) { int v = s[t]; s[t] = run; run += v; }
        g_rowptr[n] = run;
    }
    __syncthreads();
    int run = s[tid];
    for (int i = lo; i < hi; i++) {
        g_rowptr[i] = run;
        g_cursor[i] = run;
        run += g_cnt[i];
    }
}

// CSR fill: slot per (target, arrival) -> source index
__global__ void k_fill(const void* __restrict__ ei, int E, int n) {
    int e = blockIdx.x * blockDim.x + threadIdx.x;
    if (e >= E) return;
    int r, c;
    load_edge(ei, E, e, r, c);
    if ((unsigned)r >= (unsigned)n || (unsigned)c >= (unsigned)n) return;
    int pos = atomicAdd(&g_cursor[c], 1);
    g_src[pos] = r;
}

// y1 = rsqrt(deg[row]) * (x @ W1)   (deg = cnt+1 incl. self-loop)
// Packed f32x2 math; W1 staged in smem as f32-pair u64s.
__global__ void __launch_bounds__(256) k_gemm1(const float* __restrict__ x,
                                               const float* __restrict__ W,
                                               int n) {
    __shared__ __align__(16) unsigned long long sW[FIN * 8];  // 32 KB
    {
        const ulonglong2* Wv = (const ulonglong2*)W;
        ulonglong2* sWv = (ulonglong2*)sW;
        for (int i = threadIdx.x; i < FIN * 4; i += 256) sWv[i] = Wv[i];
    }
    __syncthreads();

    int row = blockIdx.x * 256 + threadIdx.x;
    if (row >= n) return;

    unsigned long long acc[8];
#pragma unroll
    for (int f = 0; f < 8; f++) acc[f] = 0ull;

    const float4* xr = (const float4*)(x + (size_t)row * FIN);
#pragma unroll 2
    for (int k4 = 0; k4 < FIN / 4; k4++) {
        float4 xv = xr[k4];
#pragma unroll
        for (int d = 0; d < 4; d++) {
            float xk = (d == 0) ? xv.x : (d == 1) ? xv.y : (d == 2) ? xv.z : xv.w;
            unsigned long long xx = pack2(xk);
            const ulonglong2* wp = (const ulonglong2*)&sW[(k4 * 4 + d) * 8];
            ulonglong2 wa = wp[0], wb = wp[1];
            acc[0] = fma2(xx, wa.x, acc[0]);
            acc[1] = fma2(xx, wa.y, acc[1]);
            acc[2] = fma2(xx, wb.x, acc[2]);
            acc[3] = fma2(xx, wb.y, acc[3]);
            ulonglong2 wc = wp[2], wd = wp[3];
            acc[4] = fma2(xx, wc.x, acc[4]);
            acc[5] = fma2(xx, wc.y, acc[5]);
            acc[6] = fma2(xx, wd.x, acc[6]);
            acc[7] = fma2(xx, wd.y, acc[7]);
        }
    }

    unsigned long long dd = pack2(rsqrtf((float)g_cnt[row] + 1.0f));
    ulonglong2* o1 = (ulonglong2*)(g_y1 + (size_t)row * F1);
#pragma unroll
    for (int q = 0; q < 4; q++) {
        ulonglong2 v;
        v.x = mul2(acc[q * 2 + 0], dd);
        v.y = mul2(acc[q * 2 + 1], dd);
        o1[q] = v;
    }
}

// layer-1 aggregation, NO atomics: thread = (node i, chunk j of 4 floats).
// acc = y1[i] (self-loop) + sum over in-edges y1[src]; coalesced single write.
__global__ void k_agg1(int n) {
    int t = blockIdx.x * blockDim.x + threadIdx.x;
    int i = t >> 2;
    int j = t & 3;
    if (i >= n) return;
    const float4* Y = (const float4*)g_y1;
    float4 acc = Y[(size_t)i * 4 + j];
    int k  = g_rowptr[i];
    int k1 = g_rowptr[i + 1];
    for (; k + 3 < k1; k += 4) {   // unroll x4 for MLP
        int r0 = g_src[k], r1 = g_src[k + 1], r2 = g_src[k + 2], r3 = g_src[k + 3];
        float4 v0 = Y[(size_t)r0 * 4 + j];
        float4 v1 = Y[(size_t)r1 * 4 + j];
        float4 v2 = Y[(size_t)r2 * 4 + j];
        float4 v3 = Y[(size_t)r3 * 4 + j];
        acc.x += v0.x + v1.x + v2.x + v3.x;
        acc.y += v0.y + v1.y + v2.y + v3.y;
        acc.z += v0.z + v1.z + v2.z + v3.z;
        acc.w += v0.w + v1.w + v2.w + v3.w;
    }
    for (; k < k1; k++) {
        int r = g_src[k];
        float4 v = Y[(size_t)r * 4 + j];
        acc.x += v.x; acc.y += v.y; acc.z += v.z; acc.w += v.w;
    }
    ((float4*)g_acc1)[(size_t)i * 4 + j] = acc;
}

// h = relu(b1 + dinv*acc1); y2 = dinv*(h @ W2)
__global__ void k_layer2(const float* __restrict__ W2,
                         const float* __restrict__ b1, int n) {
    int i = blockIdx.x * blockDim.x + threadIdx.x;
    if (i >= n) return;
    float di = rsqrtf((float)g_cnt[i] + 1.0f);
    float h[16];
    const float4* p = (const float4*)(g_acc1 + (size_t)i * F1);
#pragma unroll
    for (int q = 0; q < 4; q++) {
        float4 v = p[q];
        h[q * 4 + 0] = fmaxf(__ldg(&b1[q * 4 + 0]) + di * v.x, 0.f);
        h[q * 4 + 1] = fmaxf(__ldg(&b1[q * 4 + 1]) + di * v.y, 0.f);
        h[q * 4 + 2] = fmaxf(__ldg(&b1[q * 4 + 2]) + di * v.z, 0.f);
        h[q * 4 + 3] = fmaxf(__ldg(&b1[q * 4 + 3]) + di * v.w, 0.f);
    }
    float s[7] = {0.f, 0.f, 0.f, 0.f, 0.f, 0.f, 0.f};
#pragma unroll
    for (int k = 0; k < 16; k++) {
        float hk = h[k];
#pragma unroll
        for (int f = 0; f < 7; f++) s[f] += hk * __ldg(&W2[k * 7 + f]);
    }
    float4* oy = (float4*)(g_y2 + (size_t)i * F2P);
    oy[0] = make_float4(di * s[0], di * s[1], di * s[2], di * s[3]);
    oy[1] = make_float4(di * s[4], di * s[5], di * s[6], 0.f);
}

// layer-2 aggregation: thread = (node i, chunk j of 2)
__global__ void k_agg2(int n) {
    int t = blockIdx.x * blockDim.x + threadIdx.x;
    int i = t >> 1;
    int j = t & 1;
    if (i >= n) return;
    const float4* Y = (const float4*)g_y2;
    float4 acc = Y[(size_t)i * 2 + j];
    int k  = g_rowptr[i];
    int k1 = g_rowptr[i + 1];
    for (; k + 3 < k1; k += 4) {
        int r0 = g_src[k], r1 = g_src[k + 1], r2 = g_src[k + 2], r3 = g_src[k + 3];
        float4 v0 = Y[(size_t)r0 * 2 + j];
        float4 v1 = Y[(size_t)r1 * 2 + j];
        float4 v2 = Y[(size_t)r2 * 2 + j];
        float4 v3 = Y[(size_t)r3 * 2 + j];
        acc.x += v0.x + v1.x + v2.x + v3.x;
        acc.y += v0.y + v1.y + v2.y + v3.y;
        acc.z += v0.z + v1.z + v2.z + v3.z;
        acc.w += v0.w + v1.w + v2.w + v3.w;
    }
    for (; k < k1; k++) {
        int r = g_src[k];
        float4 v = Y[(size_t)r * 2 + j];
        acc.x += v.x; acc.y += v.y; acc.z += v.z; acc.w += v.w;
    }
    ((float4*)g_acc2)[(size_t)i * 2 + j] = acc;
}

// w = b2 + dinv*acc2; log_softmax
__global__ void k_logsoftmax(const float* __restrict__ b2,
                             float* __restrict__ out, int n) {
    int i = blockIdx.x * blockDim.x + threadIdx.x;
    if (i >= n) return;
    float di = rsqrtf((float)g_cnt[i] + 1.0f);
    const float4* p = (const float4*)(g_acc2 + (size_t)i * F2P);
    float4 a0 = p[0], a1 = p[1];
    float w[7];
    w[0] = __ldg(&b2[0]) + di * a0.x;
    w[1] = __ldg(&b2[1]) + di * a0.y;
    w[2] = __ldg(&b2[2]) + di * a0.z;
    w[3] = __ldg(&b2[3]) + di * a0.w;
    w[4] = __ldg(&b2[4]) + di * a1.x;
    w[5] = __ldg(&b2[5]) + di * a1.y;
    w[6] = __ldg(&b2[6]) + di * a1.z;
    float m = w[0];
#pragma unroll
    for (int f = 1; f < 7; f++) m = fmaxf(m, w[f]);
    float s = 0.f;
#pragma unroll
    for (int f = 0; f < 7; f++) s += expf(w[f] - m);
    float l = logf(s);
    float* o = out + (size_t)i * 7;
#pragma unroll
    for (int f = 0; f < 7; f++) o[f] = w[f] - m - l;
}

// ---------------- launch ----------------
// Inputs identified BY ELEMENT COUNT (x largest, edge_index second largest,
// W1=8192, W2=112, b1=16, b2=7); positional fallback otherwise.
extern "C" void kernel_launch(void* const* d_in, const int* in_sizes, int n_in,
                              void* d_out, int out_size) {
    const void* x  = d_in[0];
    const void* ei = d_in[1];
    const void* W1 = d_in[2];
    const void* b1 = d_in[3];
    const void* W2 = d_in[4];
    const void* b2 = d_in[5];
    int x_sz = in_sizes[0], e_sz = in_sizes[1];

    if (n_in >= 6) {
        int ix = 0;
        for (int i = 1; i < n_in; i++) if (in_sizes[i] > in_sizes[ix]) ix = i;
        int ie = (ix == 0) ? 1 : 0;
        for (int i = 0; i < n_in; i++)
            if (i != ix && in_sizes[i] > in_sizes[ie]) ie = i;
        x = d_in[ix]; x_sz = in_sizes[ix];
        ei = d_in[ie]; e_sz = in_sizes[ie];
        for (int i = 0; i < n_in; i++) {
            if (i == ix || i == ie) continue;
            switch (in_sizes[i]) {
                case 8192: W1 = d_in[i]; break;   // 512*16
                case 112:  W2 = d_in[i]; break;   // 16*7
                case 16:   b1 = d_in[i]; break;
                case 7:    b2 = d_in[i]; break;
                default: break;
            }
        }
    }

    int n = x_sz / FIN;   // 100000
    int E = e_sz / 2;     // 3200000 edges (planar [src | dst])

    const int T = 256;
    int gbN  = (n + T - 1) / T;
    int gbE  = (E + T - 1) / T;
    int gbN4 = (n * 4 + T - 1) / T;
    int gbN2 = (n * 2 + T - 1) / T;

    k_setup<<<gbN, T>>>(ei, n);
    k_count<<<gbE, T>>>(ei, E, n);
    k_scan<<<1, 1024>>>(n);
    k_fill<<<gbE, T>>>(ei, E, n);
    k_gemm1<<<gbN, T>>>((const float*)x, (const float*)W1, n);
    k_agg1<<<gbN4, T>>>(n);
    k_layer2<<<gbN, T>>>((const float*)W2, (const float*)b1, n);
    k_agg2<<<gbN2, T>>>(n);
    k_logsoftmax<<<gbN, T>>>((const float*)b2, (float*)d_out, n);
}

// round 14
// speedup vs baseline: 1.8580x; 1.8580x over previous
#include <cuda_runtime.h>
#include <cuda_fp16.h>
#include <math_constants.h>

#define NNODES 100000
#define FIN 512
#define F1 16
#define F2P 8   // 7 padded to 8

// ---------------- scratch (no allocations allowed) ----------------
__device__ __align__(16) float  g_deg[NNODES];            // degree incl. self-loop
__device__ __align__(16) __half g_y1[NNODES * F1];        // f16 gather src (32B/row)
__device__ __align__(16) __half g_acc1[NNODES * F1];      // f16 RED accumulator
__device__ __align__(16) __half g_y2[NNODES * F2P];       // 16B/row
__device__ __align__(16) __half g_acc2[NNODES * F2P];
__device__ int g_is64;   // edge dtype flag (1 = int64, 0 = int32)

// ---------------- helpers ----------------
// 8 halves (16B) per RED lane: halves LSU/LTS lane count vs f32 v4.
__device__ __forceinline__ void red_v4h(__half* p, uint4 v) {
    asm volatile("red.global.add.noftz.v4.f16x2 [%0], {%1, %2, %3, %4};"
                 :: "l"(p), "r"(v.x), "r"(v.y), "r"(v.z), "r"(v.w) : "memory");
}
__device__ __forceinline__ unsigned long long fma2(unsigned long long a,
                                                   unsigned long long b,
                                                   unsigned long long c) {
    unsigned long long d;
    asm("fma.rn.f32x2 %0, %1, %2, %3;" : "=l"(d) : "l"(a), "l"(b), "l"(c));
    return d;
}
__device__ __forceinline__ unsigned long long mul2(unsigned long long a,
                                                   unsigned long long b) {
    unsigned long long d;
    asm("mul.rn.f32x2 %0, %1, %2;" : "=l"(d) : "l"(a), "l"(b));
    return d;
}
__device__ __forceinline__ unsigned long long pack2(float x) {
    unsigned long long d;
    unsigned xi = __float_as_uint(x);
    asm("mov.b64 %0, {%1, %1};" : "=l"(d) : "r"(xi));
    return d;
}
// f32x2 (u64) -> f16x2 (u32)
__device__ __forceinline__ unsigned h2_from_u64(unsigned long long v) {
    unsigned lo, hi;
    asm("mov.b64 {%0, %1}, %2;" : "=r"(lo), "=r"(hi) : "l"(v));
    __half2 h = __floats2half2_rn(__uint_as_float(lo), __uint_as_float(hi));
    return *(unsigned*)&h;
}

// Layout: planar [all sources | all targets], E entries per block.
__device__ __forceinline__ void load_edge(const void* ei, int E, int e,
                                          int& r, int& c) {
    if (g_is64) {
        const long long* p = (const long long*)ei;
        r = (int)p[e];
        c = (int)p[(size_t)E + e];
    } else {
        const int* p = (const int*)ei;
        r = p[e];
        c = p[(size_t)E + e];
    }
}
__device__ __forceinline__ int load_col(const void* ei, int E, int e) {
    if (g_is64) return (int)((const long long*)ei)[(size_t)E + e];
    return ((const int*)ei)[(size_t)E + e];
}

// ---------------- kernels ----------------

// fused: dtype probe (global thread 0) + degree init (self-loop = 1).
__global__ void k_setup(const void* ei, int n) {
    int i = blockIdx.x * blockDim.x + threadIdx.x;
    if (i == 0) {
        const long long* p = (const long long*)ei;
        int ok = 1;
        for (int j = 0; j < 1024; j++) {
            long long v = p[j];
            if (v < 0 || v >= (long long)n) { ok = 0; break; }
        }
        g_is64 = ok;
    }
    if (i < n) g_deg[i] = 1.0f;
}

__global__ void k_deg(const void* __restrict__ ei, int E, int n) {
    int e = blockIdx.x * blockDim.x + threadIdx.x;
    if (e >= E) return;
    int c = load_col(ei, E, e);
    if ((unsigned)c >= (unsigned)n) return;
    atomicAdd(&g_deg[c], 1.0f);
}

// y1 = rsqrt(deg[row]) * (x @ W1), converted to f16, dual-stored to
// g_y1 (gather src) and g_acc1 (accumulator init = self-loop term).
__global__ void __launch_bounds__(256) k_gemm1(const float* __restrict__ x,
                                               const float* __restrict__ W,
                                               int n) {
    __shared__ __align__(16) unsigned long long sW[FIN * 8];  // 32 KB
    {
        const ulonglong2* Wv = (const ulonglong2*)W;
        ulonglong2* sWv = (ulonglong2*)sW;
        for (int i = threadIdx.x; i < FIN * 4; i += 256) sWv[i] = Wv[i];
    }
    __syncthreads();

    int row = blockIdx.x * 256 + threadIdx.x;
    if (row >= n) return;

    unsigned long long acc[8];
#pragma unroll
    for (int f = 0; f < 8; f++) acc[f] = 0ull;

    const float4* xr = (const float4*)(x + (size_t)row * FIN);
#pragma unroll 2
    for (int k4 = 0; k4 < FIN / 4; k4++) {
        float4 xv = xr[k4];
#pragma unroll
        for (int d = 0; d < 4; d++) {
            float xk = (d == 0) ? xv.x : (d == 1) ? xv.y : (d == 2) ? xv.z : xv.w;
            unsigned long long xx = pack2(xk);
            const ulonglong2* wp = (const ulonglong2*)&sW[(k4 * 4 + d) * 8];
            ulonglong2 wa = wp[0], wb = wp[1];
            acc[0] = fma2(xx, wa.x, acc[0]);
            acc[1] = fma2(xx, wa.y, acc[1]);
            acc[2] = fma2(xx, wb.x, acc[2]);
            acc[3] = fma2(xx, wb.y, acc[3]);
            ulonglong2 wc = wp[2], wd = wp[3];
            acc[4] = fma2(xx, wc.x, acc[4]);
            acc[5] = fma2(xx, wc.y, acc[5]);
            acc[6] = fma2(xx, wd.x, acc[6]);
            acc[7] = fma2(xx, wd.y, acc[7]);
        }
    }

    unsigned long long dd = pack2(rsqrtf(g_deg[row]));
    uint4 a, b;
    a.x = h2_from_u64(mul2(acc[0], dd));
    a.y = h2_from_u64(mul2(acc[1], dd));
    a.z = h2_from_u64(mul2(acc[2], dd));
    a.w = h2_from_u64(mul2(acc[3], dd));
    b.x = h2_from_u64(mul2(acc[4], dd));
    b.y = h2_from_u64(mul2(acc[5], dd));
    b.z = h2_from_u64(mul2(acc[6], dd));
    b.w = h2_from_u64(mul2(acc[7], dd));
    uint4* o1 = (uint4*)(g_y1 + (size_t)row * F1);
    uint4* o2 = (uint4*)(g_acc1 + (size_t)row * F1);
    o1[0] = a; o1[1] = b;
    o2[0] = a; o2[1] = b;
}

// layer-1 edge scatter: acc1[c] += y1[r].
// f16 transport: 2 gather lanes + 2 RED lanes per edge (vs 4+4 in f32).
__global__ void k_scatter1(const void* __restrict__ ei, int E, int n) {
    int e = blockIdx.x * blockDim.x + threadIdx.x;
    if (e >= E) return;
    int r, c;
    load_edge(ei, E, e, r, c);
    if ((unsigned)r >= (unsigned)n || (unsigned)c >= (unsigned)n) return;
    const uint4* src = (const uint4*)(g_y1 + (size_t)r * F1);
    __half* dst = g_acc1 + (size_t)c * F1;
    uint4 a = src[0], b = src[1];
    red_v4h(dst, a);
    red_v4h(dst + 8, b);
}

// h = relu(b1 + dinv*acc1); y2 = dinv*(h @ W2) in f16; dual store.
__global__ void k_layer2(const float* __restrict__ W2,
                         const float* __restrict__ b1, int n) {
    int i = blockIdx.x * blockDim.x + threadIdx.x;
    if (i >= n) return;
    float di = rsqrtf(g_deg[i]);
    const uint4* p = (const uint4*)(g_acc1 + (size_t)i * F1);
    uint4 pa = p[0], pb = p[1];
    float h[16];
    {
        unsigned u[8] = {pa.x, pa.y, pa.z, pa.w, pb.x, pb.y, pb.z, pb.w};
#pragma unroll
        for (int q = 0; q < 8; q++) {
            float2 v = __half22float2(*(__half2*)&u[q]);
            h[q * 2 + 0] = fmaxf(__ldg(&b1[q * 2 + 0]) + di * v.x, 0.f);
            h[q * 2 + 1] = fmaxf(__ldg(&b1[q * 2 + 1]) + di * v.y, 0.f);
        }
    }
    float s[7] = {0.f, 0.f, 0.f, 0.f, 0.f, 0.f, 0.f};
#pragma unroll
    for (int k = 0; k < 16; k++) {
        float hk = h[k];
#pragma unroll
        for (int f = 0; f < 7; f++) s[f] += hk * __ldg(&W2[k * 7 + f]);
    }
    uint4 o;
    {
        __half2 h0 = __floats2half2_rn(di * s[0], di * s[1]);
        __half2 h1 = __floats2half2_rn(di * s[2], di * s[3]);
        __half2 h2 = __floats2half2_rn(di * s[4], di * s[5]);
        __half2 h3 = __floats2half2_rn(di * s[6], 0.f);
        o.x = *(unsigned*)&h0; o.y = *(unsigned*)&h1;
        o.z = *(unsigned*)&h2; o.w = *(unsigned*)&h3;
    }
    *(uint4*)(g_y2 + (size_t)i * F2P) = o;
    *(uint4*)(g_acc2 + (size_t)i * F2P) = o;
}

// layer-2 edge scatter: 1 gather lane + 1 RED lane per edge.
__global__ void k_scatter2(const void* __restrict__ ei, int E, int n) {
    int e = blockIdx.x * blockDim.x + threadIdx.x;
    if (e >= E) return;
    int r, c;
    load_edge(ei, E, e, r, c);
    if ((unsigned)r >= (unsigned)n || (unsigned)c >= (unsigned)n) return;
    uint4 v = *(const uint4*)(g_y2 + (size_t)r * F2P);
    red_v4h(g_acc2 + (size_t)c * F2P, v);
}

// w = b2 + dinv*acc2; log_softmax
__global__ void k_logsoftmax(const float* __restrict__ b2,
                             float* __restrict__ out, int n) {
    int i = blockIdx.x * blockDim.x + threadIdx.x;
    if (i >= n) return;
    float di = rsqrtf(g_deg[i]);
    uint4 v = *(const uint4*)(g_acc2 + (size_t)i * F2P);
    unsigned u[4] = {v.x, v.y, v.z, v.w};
    float w[8];
#pragma unroll
    for (int q = 0; q < 4; q++) {
        float2 f = __half22float2(*(__half2*)&u[q]);
        w[q * 2 + 0] = f.x;
        w[q * 2 + 1] = f.y;
    }
#pragma unroll
    for (int f = 0; f < 7; f++) w[f] = __ldg(&b2[f]) + di * w[f];
    float m = w[0];
#pragma unroll
    for (int f = 1; f < 7; f++) m = fmaxf(m, w[f]);
    float s = 0.f;
#pragma unroll
    for (int f = 0; f < 7; f++) s += expf(w[f] - m);
    float l = logf(s);
    float* o = out + (size_t)i * 7;
#pragma unroll
    for (int f = 0; f < 7; f++) o[f] = w[f] - m - l;
}

// ---------------- launch ----------------
// Inputs identified BY ELEMENT COUNT (x largest, edge_index second largest,
// W1=8192, W2=112, b1=16, b2=7); positional fallback otherwise.
extern "C" void kernel_launch(void* const* d_in, const int* in_sizes, int n_in,
                              void* d_out, int out_size) {
    const void* x  = d_in[0];
    const void* ei = d_in[1];
    const void* W1 = d_in[2];
    const void* b1 = d_in[3];
    const void* W2 = d_in[4];
    const void* b2 = d_in[5];
    int x_sz = in_sizes[0], e_sz = in_sizes[1];

    if (n_in >= 6) {
        int ix = 0;
        for (int i = 1; i < n_in; i++) if (in_sizes[i] > in_sizes[ix]) ix = i;
        int ie = (ix == 0) ? 1 : 0;
        for (int i = 0; i < n_in; i++)
            if (i != ix && in_sizes[i] > in_sizes[ie]) ie = i;
        x = d_in[ix]; x_sz = in_sizes[ix];
        ei = d_in[ie]; e_sz = in_sizes[ie];
        for (int i = 0; i < n_in; i++) {
            if (i == ix || i == ie) continue;
            switch (in_sizes[i]) {
                case 8192: W1 = d_in[i]; break;   // 512*16
                case 112:  W2 = d_in[i]; break;   // 16*7
                case 16:   b1 = d_in[i]; break;
                case 7:    b2 = d_in[i]; break;
                default: break;
            }
        }
    }

    int n = x_sz / FIN;   // 100000
    int E = e_sz / 2;     // 3200000 edges (planar [src | dst])

    const int T = 256;
    int gbN = (n + T - 1) / T;
    int gbE = (E + T - 1) / T;

    k_setup<<<gbN, T>>>(ei, n);
    k_deg<<<gbE, T>>>(ei, E, n);
    k_gemm1<<<gbN, T>>>((const float*)x, (const float*)W1, n);
    k_scatter1<<<gbE, T>>>(ei, E, n);
    k_layer2<<<gbN, T>>>((const float*)W2, (const float*)b1, n);
    k_scatter2<<<gbE, T>>>(ei, E, n);
    k_logsoftmax<<<gbN, T>>>((const float*)b2, (float*)d_out, n);
}